// round 5
// baseline (speedup 1.0000x reference)
#include <cuda_runtime.h>

// ============================================================================
// Fused scaled-dot-product attention (fp32), B=2 H=16 S=2048 D=64.
// Outputs: d_out[0 : B*H*S*D)          = context
//          d_out[B*H*S*D : +B*H*S*S)   = attention (post-softmax)
//
// One block (512 threads, 16 warps) = one (b*h, 16-query-row) tile.
// 16 warps/SM (4 per SMSP) to hide LDS/issue latency that capped the
// 256-thread version at issue=27%.
// ============================================================================

namespace {

constexpr int Bc  = 2;
constexpr int Hc  = 16;
constexpr int Sc  = 2048;
constexpr int Dc  = 64;
constexpr int TQ  = 16;    // query rows per block
constexpr int KTW = 256;   // K-tile width (score columns per supertile)
constexpr int KP  = 65;    // K smem pitch (odd -> conflict-free column reads)
constexpr int SP  = 2052;  // score row pitch
constexpr int NT  = 512;   // threads per block (16 warps)

constexpr int SM_QT     = 0;                   // Qt[d][q]  : 64*16 = 1024
constexpr int SM_INV    = SM_QT + Dc * TQ;     // inv[16]
constexpr int SM_SC     = SM_INV + 16;         // SC[q][SP] : 16*2052
constexpr int SM_KV     = SM_SC + TQ * SP;     // KV: K tile 256*65 / V tile / partials
constexpr int SM_FLOATS = SM_KV + KTW * KP;    // 50512 floats = 202048 bytes

__device__ __forceinline__ unsigned long long pk2(float x, float y) {
    unsigned long long r;
    asm("mov.b64 %0, {%1, %2};"
        : "=l"(r) : "r"(__float_as_uint(x)), "r"(__float_as_uint(y)));
    return r;
}

__device__ __forceinline__ void upk2(unsigned long long v, float& x, float& y) {
    unsigned int a, b;
    asm("mov.b64 {%0, %1}, %2;" : "=r"(a), "=r"(b) : "l"(v));
    x = __uint_as_float(a);
    y = __uint_as_float(b);
}

__device__ __forceinline__ unsigned long long
fma2(unsigned long long a, unsigned long long b, unsigned long long c) {
    unsigned long long d;
    asm("fma.rn.f32x2 %0, %1, %2, %3;" : "=l"(d) : "l"(a), "l"(b), "l"(c));
    return d;
}

} // namespace

__global__ void __launch_bounds__(NT, 1)
attn_fused_kernel(const float* __restrict__ Q, const float* __restrict__ K,
                  const float* __restrict__ V, const float* __restrict__ M,
                  float* __restrict__ OC, float* __restrict__ OA)
{
    extern __shared__ float sm[];
    float* Qt    = sm + SM_QT;
    float* sminv = sm + SM_INV;
    float* SC    = sm + SM_SC;
    float* KV    = sm + SM_KV;

    const int t  = threadIdx.x;
    const int qt = blockIdx.x;   // query tile (0..127)
    const int bh = blockIdx.y;   // b*H + h    (0..31)

    const float* Qb = Q + ((long)bh * Sc + qt * TQ) * Dc;
    const float* Kb = K + (long)bh * Sc * Dc;
    const float* Vb = V + (long)bh * Sc * Dc;
    const float* Mb = M + ((long)bh * Sc + (long)qt * TQ) * Sc;
    float*       Ab = OA + ((long)bh * Sc + (long)qt * TQ) * Sc;
    float*       Cb = OC + ((long)bh * Sc + qt * TQ) * Dc;

    // ---------------- Phase 0: stage Q transposed (Qt[d][q]) ----------------
    if (t < 256) {
        const int q  = t >> 4;          // 0..15
        const int d0 = (t & 15) << 2;   // 0,4,...,60
        float4 v = *reinterpret_cast<const float4*>(Qb + q * Dc + d0);
        Qt[(d0 + 0) * TQ + q] = v.x;
        Qt[(d0 + 1) * TQ + q] = v.y;
        Qt[(d0 + 2) * TQ + q] = v.z;
        Qt[(d0 + 3) * TQ + q] = v.w;
    }

    const int a = t >> 8;    // q octet: rows 8a..8a+7
    const int g = t & 255;   // k column within supertile

    // ---------------- Phase 1: S = (Q K^T) * 1/sqrt(D) ----------------------
    const float scl = 0.125f;  // 1/sqrt(64)
    for (int st = 0; st < Sc / KTW; ++st) {
        __syncthreads();
        // Load K supertile rows [st*256, +256) into KV[k][KP], coalesced LDG.
        {
            const float* src = Kb + (long)st * KTW * Dc;
            #pragma unroll
            for (int ii = 0; ii < (KTW * Dc) / (NT * 4); ++ii) {  // 8 iters
                const int idx4 = t + NT * ii;
                const int kr = idx4 >> 4;
                const int d0 = (idx4 & 15) << 2;
                float4 v = *reinterpret_cast<const float4*>(src + (size_t)idx4 * 4);
                float* dst = KV + kr * KP + d0;
                dst[0] = v.x; dst[1] = v.y; dst[2] = v.z; dst[3] = v.w;
            }
        }
        __syncthreads();

        // acc[j]: q-pair j (rows 8a+2j, 8a+2j+1) for this thread's column g.
        unsigned long long a0 = 0ull, a1 = 0ull, a2 = 0ull, a3 = 0ull;
        const float* kcol = KV + g * KP;
        #pragma unroll 8
        for (int d = 0; d < Dc; ++d) {
            const ulonglong2 qA =
                *reinterpret_cast<const ulonglong2*>(Qt + d * TQ + 8 * a);
            const ulonglong2 qB =
                *reinterpret_cast<const ulonglong2*>(Qt + d * TQ + 8 * a + 4);
            const float k = kcol[d];
            const unsigned long long kk = pk2(k, k);
            a0 = fma2(qA.x, kk, a0);
            a1 = fma2(qA.y, kk, a1);
            a2 = fma2(qB.x, kk, a2);
            a3 = fma2(qB.y, kk, a3);
        }

        {
            float s0, s1;
            float* col = SC + st * KTW + g;
            upk2(a0, s0, s1);
            col[(8*a + 0) * SP] = s0 * scl;  col[(8*a + 1) * SP] = s1 * scl;
            upk2(a1, s0, s1);
            col[(8*a + 2) * SP] = s0 * scl;  col[(8*a + 3) * SP] = s1 * scl;
            upk2(a2, s0, s1);
            col[(8*a + 4) * SP] = s0 * scl;  col[(8*a + 5) * SP] = s1 * scl;
            upk2(a3, s0, s1);
            col[(8*a + 6) * SP] = s0 * scl;  col[(8*a + 7) * SP] = s1 * scl;
        }
    }
    __syncthreads();

    // ------- Softmax (+mask): leave UNNORMALIZED exp in SC; write attention -
    {
        const int r = t >> 5, lane = t & 31;    // 16 warps -> 16 rows
        float* row = SC + r * SP;
        const float* mrow = Mb + (long)r * Sc;

        float mx = -3.0e38f;
        #pragma unroll
        for (int i = 0; i < Sc / 128; ++i) {  // 16 iters of float4
            const int c = (lane + i * 32) << 2;
            float4 s = *reinterpret_cast<float4*>(row + c);
            const float4 m = *reinterpret_cast<const float4*>(mrow + c);
            s.x += m.x; s.y += m.y; s.z += m.z; s.w += m.w;
            *reinterpret_cast<float4*>(row + c) = s;
            mx = fmaxf(mx, fmaxf(fmaxf(s.x, s.y), fmaxf(s.z, s.w)));
        }
        #pragma unroll
        for (int o = 16; o > 0; o >>= 1)
            mx = fmaxf(mx, __shfl_xor_sync(0xffffffffu, mx, o));

        float sum = 0.f;
        #pragma unroll
        for (int i = 0; i < Sc / 128; ++i) {
            const int c = (lane + i * 32) << 2;
            float4 s = *reinterpret_cast<float4*>(row + c);
            s.x = __expf(s.x - mx); s.y = __expf(s.y - mx);
            s.z = __expf(s.z - mx); s.w = __expf(s.w - mx);
            *reinterpret_cast<float4*>(row + c) = s;   // unnormalized exp
            sum += (s.x + s.y) + (s.z + s.w);
        }
        #pragma unroll
        for (int o = 16; o > 0; o >>= 1)
            sum += __shfl_xor_sync(0xffffffffu, sum, o);
        const float inv = 1.0f / sum;
        if (lane == 0) sminv[r] = inv;

        float* arow = Ab + (long)r * Sc;
        #pragma unroll
        for (int i = 0; i < Sc / 128; ++i) {
            const int c = (lane + i * 32) << 2;
            float4 s = *reinterpret_cast<float4*>(row + c);
            s.x *= inv; s.y *= inv; s.z *= inv; s.w *= inv;
            *reinterpret_cast<float4*>(arow + c) = s;  // attention out only
        }
    }

    // ---------------- Phase 2: C = P @ V (P = unnormalized exp) -------------
    const int p  = t >> 5;         // warp id: k rows p*8..p*8+7 per V tile
    const int a2 = (t >> 4) & 1;   // q octet: rows 8*a2..8*a2+7
    const int dg = t & 15;         // d quad : cols 4*dg..4*dg+3

    unsigned long long cA[8], cB[8];   // per q-row r: (d0,d1) and (d2,d3)
    #pragma unroll
    for (int r = 0; r < 8; ++r) { cA[r] = 0ull; cB[r] = 0ull; }

    for (int vt = 0; vt < Sc / 128; ++vt) {   // 16 V tiles of 128 rows
        __syncthreads();
        {
            const float4* src =
                reinterpret_cast<const float4*>(Vb + (long)vt * 128 * Dc);
            float4* dst = reinterpret_cast<float4*>(KV);
            #pragma unroll
            for (int ii = 0; ii < (128 * Dc) / (NT * 4); ++ii)  // 4 iters
                dst[t + NT * ii] = src[t + NT * ii];
        }
        __syncthreads();

        const float* pcb = SC + vt * 128 + p * 8;
        #pragma unroll
        for (int kk = 0; kk < 8; kk += 2) {
            const float* vrow = KV + (p * 8 + kk) * Dc + 4 * dg;
            const ulonglong2 v0 = *reinterpret_cast<const ulonglong2*>(vrow);
            const ulonglong2 v1 = *reinterpret_cast<const ulonglong2*>(vrow + Dc);
            #pragma unroll
            for (int r = 0; r < 8; ++r) {
                const float2 pv =
                    *reinterpret_cast<const float2*>(pcb + (8*a2 + r) * SP + kk);
                const unsigned long long pa = pk2(pv.x, pv.x);
                const unsigned long long pb = pk2(pv.y, pv.y);
                cA[r] = fma2(pa, v0.x, cA[r]);
                cB[r] = fma2(pa, v0.y, cB[r]);
                cA[r] = fma2(pb, v1.x, cA[r]);
                cB[r] = fma2(pb, v1.y, cB[r]);
            }
        }
    }

    // Scale partials by 1/sum, store per-warp partials, reduce over 16 slices.
    __syncthreads();
    #pragma unroll
    for (int r = 0; r < 8; ++r) {
        const int row = 8 * a2 + r;
        const float inv = sminv[row];
        float s0, s1, s2, s3;
        upk2(cA[r], s0, s1);
        upk2(cB[r], s2, s3);
        *reinterpret_cast<float4*>(KV + p * 1024 + row * Dc + 4 * dg) =
            make_float4(s0 * inv, s1 * inv, s2 * inv, s3 * inv);
    }
    __syncthreads();
    {
        // 1024 context floats = 512 float2 slots; one per thread.
        const float2* kv2 = reinterpret_cast<const float2*>(KV);
        float2 o = make_float2(0.f, 0.f);
        #pragma unroll
        for (int pp = 0; pp < 16; ++pp) {
            const float2 r = kv2[pp * 512 + t];
            o.x += r.x; o.y += r.y;
        }
        reinterpret_cast<float2*>(Cb)[t] = o;
    }
}

extern "C" void kernel_launch(void* const* d_in, const int* in_sizes, int n_in,
                              void* d_out, int out_size) {
    const float* Q = (const float*)d_in[0];
    const float* K = (const float*)d_in[1];
    const float* V = (const float*)d_in[2];
    const float* M = (const float*)d_in[3];

    float* ctx  = (float*)d_out;
    float* attn = (float*)d_out + (size_t)Bc * Hc * Sc * Dc;  // context, then attention

    const size_t smem_bytes = (size_t)SM_FLOATS * sizeof(float);
    cudaFuncSetAttribute(attn_fused_kernel,
                         cudaFuncAttributeMaxDynamicSharedMemorySize,
                         (int)smem_bytes);

    dim3 grid(Sc / TQ, Bc * Hc);   // (128, 32)
    attn_fused_kernel<<<grid, NT, smem_bytes>>>(Q, K, V, M, ctx, attn);
}

// round 7
// speedup vs baseline: 1.9675x; 1.9675x over previous
#include <cuda_runtime.h>
#include <cuda_bf16.h>
#include <cstdint>

namespace {
constexpr int Sd = 2048, Dd = 64, QT = 64, CH = 64, NCH = Sd / CH, NT = 128;
constexpr int PIT = 72;                      // bf16 row pitch (conflict-free LDSM)
constexpr int TILE = QT * PIT * 2;           // 9216 bytes per bf16 tile
constexpr int SQH = 0, SQL = TILE;           // Q hi/lo
constexpr int SK = 2 * TILE;                 // K: 2 bufs x (hi+lo)
constexpr int SV = SK + 4 * TILE;            // V: 2 bufs x (hi+lo)
constexpr int SMEM_BYTES = SV + 4 * TILE;    // 92160

__device__ float g_inv[65536];

__device__ __forceinline__ uint32_t smem_u32(const void* p) {
    uint32_t a;
    asm("{ .reg .u64 t; cvta.to.shared.u64 t, %1; cvt.u32.u64 %0, t; }"
        : "=r"(a) : "l"(p));
    return a;
}
__device__ __forceinline__ uint32_t pack2(float a, float b) {  // lo=a, hi=b
    uint32_t r;
    asm("cvt.rn.bf16x2.f32 %0, %1, %2;" : "=r"(r) : "f"(b), "f"(a));
    return r;
}
__device__ __forceinline__ float bfr(float x) {
    return __bfloat162float(__float2bfloat16(x));
}
__device__ __forceinline__ void ldm_x4(uint32_t a, uint32_t* r) {
    asm volatile("ldmatrix.sync.aligned.m8n8.x4.shared.b16 {%0,%1,%2,%3}, [%4];"
                 : "=r"(r[0]), "=r"(r[1]), "=r"(r[2]), "=r"(r[3]) : "r"(a));
}
__device__ __forceinline__ void ldm_x2(uint32_t a, uint32_t* r) {
    asm volatile("ldmatrix.sync.aligned.m8n8.x2.shared.b16 {%0,%1}, [%2];"
                 : "=r"(r[0]), "=r"(r[1]) : "r"(a));
}
__device__ __forceinline__ void ldm_x2t(uint32_t a, uint32_t* r) {
    asm volatile("ldmatrix.sync.aligned.m8n8.x2.trans.shared.b16 {%0,%1}, [%2];"
                 : "=r"(r[0]), "=r"(r[1]) : "r"(a));
}
__device__ __forceinline__ void mma_bf16(float* d, const uint32_t* a,
                                         const uint32_t* b) {
    asm volatile(
        "mma.sync.aligned.m16n8k16.row.col.f32.bf16.bf16.f32 "
        "{%0,%1,%2,%3}, {%4,%5,%6,%7}, {%8,%9}, {%0,%1,%2,%3};"
        : "+f"(d[0]), "+f"(d[1]), "+f"(d[2]), "+f"(d[3])
        : "r"(a[0]), "r"(a[1]), "r"(a[2]), "r"(a[3]), "r"(b[0]), "r"(b[1]));
}

// [64 x 64] fp32 -> bf16 hi/lo tiles, pitch-72 rows.
__device__ __forceinline__ void load_conv(const float* __restrict__ src,
                                          char* sm, int offH, int offL,
                                          int t, float scale) {
    #pragma unroll
    for (int i = 0; i < 8; ++i) {
        const int idx4 = t + NT * i;
        const int row = idx4 >> 4, c4 = (idx4 & 15) << 2;
        float4 v = *(const float4*)(src + (size_t)idx4 * 4);
        v.x *= scale; v.y *= scale; v.z *= scale; v.w *= scale;
        const float hx = bfr(v.x), hy = bfr(v.y), hz = bfr(v.z), hw = bfr(v.w);
        const int boff = (row * PIT + c4) * 2;
        *(uint2*)(sm + offH + boff) = make_uint2(pack2(v.x, v.y), pack2(v.z, v.w));
        *(uint2*)(sm + offL + boff) =
            make_uint2(pack2(v.x - hx, v.y - hy), pack2(v.z - hz, v.w - hw));
    }
}
} // namespace

__global__ void __launch_bounds__(NT)
attn_mma_kernel(const float* __restrict__ Q, const float* __restrict__ K,
                const float* __restrict__ V, const float* __restrict__ Mk,
                float* __restrict__ OC, float* __restrict__ OA)
{
    extern __shared__ char smem[];
    const uint32_t sb = smem_u32(smem);

    const int t = threadIdx.x, w = t >> 5, l = t & 31;
    const int gid = l >> 2, qd = l & 3;
    const int qt = blockIdx.x, bh = blockIdx.y;

    const float* Qb = Q + ((long)bh * Sd + qt * QT) * Dd;
    const float* Kb = K + (long)bh * Sd * Dd;
    const float* Vb = V + (long)bh * Sd * Dd;
    const float* Mb = Mk + ((long)bh * Sd + qt * QT) * Sd;
    float*       Ab = OA + ((long)bh * Sd + qt * QT) * Sd;
    float*       Cb = OC + ((long)bh * Sd + qt * QT) * Dd;

    // Stage Q (x 1/8) and chunk 0 of K/V.
    load_conv(Qb, smem, SQH, SQL, t, 0.125f);
    load_conv(Kb, smem, SK, SK + TILE, t, 1.0f);
    load_conv(Vb, smem, SV, SV + TILE, t, 1.0f);
    __syncthreads();

    // Q fragments (A operand), 4 k-tiles, hi/lo.
    uint32_t qh[4][4], ql[4][4];
    {
        const int rowb = ((16 * w + (l & 15)) * PIT + ((l >> 4) << 3)) * 2;
        #pragma unroll
        for (int kt = 0; kt < 4; ++kt) {
            ldm_x4(sb + SQH + rowb + kt * 32, qh[kt]);
            ldm_x4(sb + SQL + rowb + kt * 32, ql[kt]);
        }
    }

    float ctx[8][4];
    #pragma unroll
    for (int d = 0; d < 8; ++d)
        { ctx[d][0] = 0.f; ctx[d][1] = 0.f; ctx[d][2] = 0.f; ctx[d][3] = 0.f; }
    float rs0 = 0.f, rs1 = 0.f;

    const int l2 = l & 15;
    // K B-frag lane offset: row = nt*8 + (l2&7), col = kt*16 + (l2>>3)*8
    const int koff = ((l2 & 7) * PIT + ((l2 >> 3) << 3)) * 2;
    // V B-frag (trans): row = kt*16 + l2, col = dt*8
    const int voff = (l2 * PIT) * 2;

    const float* mrow = Mb + (long)(16 * w + gid) * Sd + 2 * qd;
    float*       arow = Ab + (long)(16 * w + gid) * Sd + 2 * qd;

    for (int c = 0; c < NCH; ++c) {
        const int buf = c & 1;
        if (c + 1 < NCH) {
            load_conv(Kb + (long)(c + 1) * CH * Dd, smem,
                      SK + (buf ^ 1) * 2 * TILE, SK + (buf ^ 1) * 2 * TILE + TILE,
                      t, 1.0f);
            load_conv(Vb + (long)(c + 1) * CH * Dd, smem,
                      SV + (buf ^ 1) * 2 * TILE, SV + (buf ^ 1) * 2 * TILE + TILE,
                      t, 1.0f);
        }

        const uint32_t kh_base = sb + SK + buf * 2 * TILE + koff;
        const uint32_t kl_base = kh_base + TILE;
        const uint32_t vh_base = sb + SV + buf * 2 * TILE + voff;
        const uint32_t vl_base = vh_base + TILE;
        const int cb = c * CH;

        uint32_t Ph[16], Pl[16];
        #pragma unroll
        for (int nt = 0; nt < 8; ++nt) {
            float s[4] = {0.f, 0.f, 0.f, 0.f};
            #pragma unroll
            for (int kt = 0; kt < 4; ++kt) {
                const uint32_t off = (uint32_t)(nt * 8 * PIT * 2 + kt * 32);
                uint32_t kh[2], kl[2];
                ldm_x2(kh_base + off, kh);
                ldm_x2(kl_base + off, kl);
                mma_bf16(s, qh[kt], kh);
                mma_bf16(s, qh[kt], kl);
                mma_bf16(s, ql[kt], kh);
            }
            const float2 m0 = *(const float2*)(mrow + cb + nt * 8);
            const float2 m1 = *(const float2*)(mrow + cb + nt * 8 + 8 * (long)Sd);
            const float e0 = __expf(s[0] + m0.x), e1 = __expf(s[1] + m0.y);
            const float e2 = __expf(s[2] + m1.x), e3 = __expf(s[3] + m1.y);
            rs0 += e0 + e1; rs1 += e2 + e3;
            *(float2*)(arow + cb + nt * 8) = make_float2(e0, e1);
            *(float2*)(arow + cb + nt * 8 + 8 * (long)Sd) = make_float2(e2, e3);
            const float h0 = bfr(e0), h1 = bfr(e1), h2 = bfr(e2), h3 = bfr(e3);
            Ph[2 * nt]     = pack2(e0, e1);
            Ph[2 * nt + 1] = pack2(e2, e3);
            Pl[2 * nt]     = pack2(e0 - h0, e1 - h1);
            Pl[2 * nt + 1] = pack2(e2 - h2, e3 - h3);
        }

        #pragma unroll
        for (int kt = 0; kt < 4; ++kt) {
            const uint32_t* ah = Ph + 4 * kt;
            const uint32_t* al = Pl + 4 * kt;
            const uint32_t vrow = (uint32_t)(kt * 16 * PIT * 2);
            #pragma unroll
            for (int dt = 0; dt < 8; ++dt) {
                uint32_t vh[2], vl[2];
                ldm_x2t(vh_base + vrow + dt * 16, vh);
                ldm_x2t(vl_base + vrow + dt * 16, vl);
                mma_bf16(ctx[dt], ah, vh);
                mma_bf16(ctx[dt], ah, vl);
                mma_bf16(ctx[dt], al, vh);
            }
        }
        __syncthreads();
    }

    // Rowsum reduce across quad lanes, normalize context, save 1/sum.
    #pragma unroll
    for (int o = 1; o < 4; o <<= 1) {
        rs0 += __shfl_xor_sync(0xffffffffu, rs0, o);
        rs1 += __shfl_xor_sync(0xffffffffu, rs1, o);
    }
    const float inv0 = 1.0f / rs0, inv1 = 1.0f / rs1;
    const int grow = bh * Sd + qt * QT + 16 * w + gid;
    if (qd == 0) {
        g_inv[grow]     = inv0;
        g_inv[grow + 8] = inv1;
    }
    {
        float* crow = Cb + (long)(16 * w + gid) * Dd + 2 * qd;
        #pragma unroll
        for (int dt = 0; dt < 8; ++dt) {
            *(float2*)(crow + dt * 8) =
                make_float2(ctx[dt][0] * inv0, ctx[dt][1] * inv0);
            *(float2*)(crow + dt * 8 + 8 * Dd) =
                make_float2(ctx[dt][2] * inv1, ctx[dt][3] * inv1);
        }
    }
}

__global__ void __launch_bounds__(256, 8)
attn_norm_kernel(float* __restrict__ A)
{
    const size_t i = ((size_t)blockIdx.x * 256 + threadIdx.x) * 4;
    const int row = (int)(i >> 11);
    float4 v = *(float4*)(A + i);
    const float s = g_inv[row];
    v.x *= s; v.y *= s; v.z *= s; v.w *= s;
    *(float4*)(A + i) = v;
}

extern "C" void kernel_launch(void* const* d_in, const int* in_sizes, int n_in,
                              void* d_out, int out_size) {
    const float* Q = (const float*)d_in[0];
    const float* K = (const float*)d_in[1];
    const float* V = (const float*)d_in[2];
    const float* M = (const float*)d_in[3];

    float* ctx  = (float*)d_out;
    float* attn = (float*)d_out + (size_t)2 * 16 * 2048 * 64;

    cudaFuncSetAttribute(attn_mma_kernel,
                         cudaFuncAttributeMaxDynamicSharedMemorySize, SMEM_BYTES);

    dim3 grid(Sd / QT, 32);   // (32, 32)
    attn_mma_kernel<<<grid, NT, SMEM_BYTES>>>(Q, K, V, M, ctx, attn);

    const size_t total4 = (size_t)32 * 2048 * 2048 / 4;
    attn_norm_kernel<<<(unsigned)(total4 / 256), 256>>>(attn);
}